// round 13
// baseline (speedup 1.0000x reference)
#include <cuda_runtime.h>
#include <cuda_bf16.h>
#include <cstdint>

#define NN 50000
#define EE 800000
#define BCAP 64           // max in-degree ~38 (Binomial mean 16, sigma 4); 64 is >6-sigma safe
#define GT 391            // 128-row GEMM CTAs
#define GB 1563           // bucket-build blocks (512 edges each)

// ---------------- scratch (static device globals; no allocation) ----------------
__device__ int   g_cnt[NN];
__device__ int   g_bucket[(size_t)NN * BCAP];
__device__ float g_dinv[NN];
__device__ float g_h2 [(size_t)NN * 64];
__device__ float g_S1 [(size_t)NN * 64];
__device__ float g_S2 [(size_t)NN * 64];
__device__ float g_c1 [(size_t)NN * 64];
__device__ float g_c2 [(size_t)NN * 64];

__device__ __forceinline__ uint32_t pack_bf16(float a, float b) {
    __nv_bfloat162 t = __floats2bfloat162_rn(a, b);
    return *reinterpret_cast<uint32_t*>(&t);
}

__device__ __forceinline__ void split2(float a, float b, uint32_t& hi, uint32_t& lo) {
    __nv_bfloat16 ah = __float2bfloat16(a), bh = __float2bfloat16(b);
    __nv_bfloat162 hv; hv.x = ah; hv.y = bh;
    hi = *reinterpret_cast<uint32_t*>(&hv);
    lo = pack_bf16(a - __bfloat162float(ah), b - __bfloat162float(bh));
}

__device__ __forceinline__ void split4store(uint32_t* Hi, uint32_t* Lo, int w, float4 v) {
    uint32_t h0, l0, h1, l1;
    split2(v.x, v.y, h0, l0);
    split2(v.z, v.w, h1, l1);
    Hi[w] = h0; Hi[w + 1] = h1;
    Lo[w] = l0; Lo[w + 1] = l1;
}

__device__ __forceinline__ void mma16816(float* c, const uint32_t* a, uint32_t b0, uint32_t b1) {
    asm volatile(
        "mma.sync.aligned.m16n8k16.row.col.f32.bf16.bf16.f32 "
        "{%0,%1,%2,%3}, {%4,%5,%6,%7}, {%8,%9}, {%0,%1,%2,%3};"
        : "+f"(c[0]), "+f"(c[1]), "+f"(c[2]), "+f"(c[3])
        : "r"(a[0]), "r"(a[1]), "r"(a[2]), "r"(a[3]), "r"(b0), "r"(b1));
}

__device__ __forceinline__ void ldsm_x4(uint32_t addr, uint32_t* r) {
    asm volatile("ldmatrix.sync.aligned.m8n8.x4.shared.b16 {%0,%1,%2,%3}, [%4];"
                 : "=r"(r[0]), "=r"(r[1]), "=r"(r[2]), "=r"(r[3]) : "r"(addr));
}
__device__ __forceinline__ void ldsm_x2(uint32_t addr, uint32_t* r) {
    asm volatile("ldmatrix.sync.aligned.m8n8.x2.shared.b16 {%0,%1}, [%2];"
                 : "=r"(r[0]), "=r"(r[1]) : "r"(addr));
}

// 3-term bf16 split mainloop; PW/4 must be odd for conflict-free LDSM.
template <int PW, int NK>
__device__ __forceinline__ void run_mainloop(uint32_t smbase, int TA_w, int TB_w,
                                             int baseB_w, int wrow, int nt0,
                                             int lane, float acc[4][4]) {
    const int mA = lane >> 3;
    const uint32_t aH = smbase + (((wrow + (lane & 7) + (mA & 1) * 8) * PW + (mA >> 1) * 4) << 2);
    const uint32_t aL = aH + (TA_w << 2);
    const int l15 = lane & 15;
    uint32_t bH[4], bL[4];
#pragma unroll
    for (int nt = 0; nt < 4; nt++) {
        bH[nt] = smbase + ((baseB_w + ((nt0 + nt) * 8 + (l15 & 7)) * PW + (l15 >> 3) * 4) << 2);
        bL[nt] = bH[nt] + (TB_w << 2);
    }
#pragma unroll
    for (int ks = 0; ks < NK; ks++) {
        const uint32_t kb = (uint32_t)ks * 32;
        uint32_t ah[4], al[4];
        ldsm_x4(aH + kb, ah);
        ldsm_x4(aL + kb, al);
#pragma unroll
        for (int nt = 0; nt < 4; nt++) {
            uint32_t bh[2], bl[2];
            ldsm_x2(bH[nt] + kb, bh);
            ldsm_x2(bL[nt] + kb, bl);
            mma16816(acc[nt], ah, bh[0], bh[1]);
            mma16816(acc[nt], al, bh[0], bh[1]);
            mma16816(acc[nt], ah, bl[0], bl[1]);
        }
    }
}

__global__ void dinv_kernel() {
    int i = blockIdx.x * 256 + threadIdx.x;
    if (i >= NN) return;
    int c = g_cnt[i];
    float d = (float)(c > 0 ? c : 1);
    g_dinv[i] = rsqrtf(d);
}

// =========== K-chunked cat-GEMM: out = relu([h|-S1|2S2-h] @ W[64,192]^T + b) =========
template <int KD, int KC, int CAT>
__global__ void __launch_bounds__(512) gemm_mma_kernel(const float* __restrict__ X,
                                                       const float* __restrict__ S1,
                                                       const float* __restrict__ S2,
                                                       const float* __restrict__ W,
                                                       const float* __restrict__ bias,
                                                       float* __restrict__ out,
                                                       int do_relu) {
    constexpr int PW = KC / 2 + 4;
    constexpr int TA = 128 * PW, TB = 64 * PW;
    constexpr int NCH = KD / KC, NK = KC / 16, KQ = KC / 4;
    extern __shared__ uint32_t sm[];
    __shared__ float bsh[64];

    const int tid = threadIdx.x;
    const long row0 = (long)blockIdx.x * 128;
    if (tid < 64) bsh[tid] = bias[tid];

    const int warp = tid >> 5, lane = tid & 31;
    const int wrow = (warp & 7) * 16;
    const int nt0 = (warp >> 3) * 4;
    const uint32_t smbase = (uint32_t)__cvta_generic_to_shared(sm);

    float acc[4][4];
#pragma unroll
    for (int nt = 0; nt < 4; nt++)
#pragma unroll
        for (int j = 0; j < 4; j++) acc[nt][j] = 0.f;

#pragma unroll
    for (int ch = 0; ch < NCH; ch++) {
        if (ch) __syncthreads();
        for (int q = tid; q < 128 * KQ; q += 512) {
            int r = q / KQ, cl = (q % KQ) * 4, gc = ch * KC + cl;
            long gr = row0 + r; if (gr >= NN) gr = NN - 1;
            float4 v;
            if (CAT) {
                if (gc < 64) {
                    v = *(const float4*)(X + gr * 64 + gc);
                } else if (gc < 128) {
                    float4 s = *(const float4*)(S1 + gr * 64 + (gc - 64));
                    v = make_float4(-s.x, -s.y, -s.z, -s.w);
                } else {
                    float4 s = *(const float4*)(S2 + gr * 64 + (gc - 128));
                    float4 h = *(const float4*)(X + gr * 64 + (gc - 128));
                    v = make_float4(fmaf(2.f, s.x, -h.x), fmaf(2.f, s.y, -h.y),
                                    fmaf(2.f, s.z, -h.z), fmaf(2.f, s.w, -h.w));
                }
            } else {
                v = *(const float4*)(X + gr * KD + gc);
            }
            split4store(sm, sm + TA, r * PW + (cl >> 1), v);
        }
        for (int q = tid; q < 64 * KQ; q += 512) {
            int r = q / KQ, cl = (q % KQ) * 4, gc = ch * KC + cl;
            float4 v = *(const float4*)(W + (long)r * KD + gc);
            split4store(sm + 2 * TA, sm + 2 * TA + TB, r * PW + (cl >> 1), v);
        }
        __syncthreads();
        run_mainloop<PW, NK>(smbase, TA, TB, 2 * TA, wrow, nt0, lane, acc);
    }

    const int rA = lane >> 2, kq = lane & 3;
    const long r_lo = row0 + wrow + rA, r_hi = r_lo + 8;
#pragma unroll
    for (int nt = 0; nt < 4; nt++) {
        int col = (nt0 + nt) * 8 + kq * 2;
        float2 v0 = make_float2(acc[nt][0] + bsh[col], acc[nt][1] + bsh[col + 1]);
        float2 v1 = make_float2(acc[nt][2] + bsh[col], acc[nt][3] + bsh[col + 1]);
        if (do_relu) {
            v0.x = fmaxf(v0.x, 0.f); v0.y = fmaxf(v0.y, 0.f);
            v1.x = fmaxf(v1.x, 0.f); v1.y = fmaxf(v1.y, 0.f);
        }
        if (r_lo < NN) *(float2*)(out + r_lo * 64 + col) = v0;
        if (r_hi < NN) *(float2*)(out + r_hi * 64 + col) = v1;
    }
}

// =========== fused front MLP + bucket build ===========
__global__ void __launch_bounds__(512) front_build_kernel(const float* __restrict__ X,
                                                          const float* __restrict__ W1,
                                                          const float* __restrict__ b1,
                                                          const float* __restrict__ W2,
                                                          const float* __restrict__ b2,
                                                          float* __restrict__ out,
                                                          const int* __restrict__ src,
                                                          const int* __restrict__ dst) {
    extern __shared__ uint32_t sm[];
    const int b = blockIdx.x;
    const int tid = threadIdx.x;

    if (b >= GT) {                               // bucket build
        int e = (b - GT) * 512 + tid;
        if (e < EE) {
            int d = dst[e];
            int p = atomicAdd(&g_cnt[d], 1);
            if (p < BCAP) g_bucket[(size_t)d * BCAP + p] = src[e];
        }
        return;
    }

    constexpr int PW1 = 68, TA1 = 128 * PW1, TB1 = 64 * PW1;
    constexpr int PW2 = 36, TA2 = 128 * PW2, TB2 = 64 * PW2;
    __shared__ float bsh1[64], bsh2[64];
    const long row0 = (long)b * 128;
    if (tid < 64) { bsh1[tid] = b1[tid]; bsh2[tid] = b2[tid]; }

    for (int q = tid; q < 128 * 32; q += 512) {
        int r = q >> 5, c = (q & 31) * 4;
        long gr = row0 + r; if (gr >= NN) gr = NN - 1;
        float4 v = *(const float4*)(X + gr * 128 + c);
        split4store(sm, sm + TA1, r * PW1 + (c >> 1), v);
    }
    for (int q = tid; q < 64 * 32; q += 512) {
        int r = q >> 5, c = (q & 31) * 4;
        float4 v = *(const float4*)(W1 + (long)r * 128 + c);
        split4store(sm + 2 * TA1, sm + 2 * TA1 + TB1, r * PW1 + (c >> 1), v);
    }
    __syncthreads();

    const int warp = tid >> 5, lane = tid & 31;
    const int wrow = (warp & 7) * 16;
    const int nt0 = (warp >> 3) * 4;
    const uint32_t smbase = (uint32_t)__cvta_generic_to_shared(sm);

    float acc[4][4];
#pragma unroll
    for (int nt = 0; nt < 4; nt++)
#pragma unroll
        for (int j = 0; j < 4; j++) acc[nt][j] = 0.f;
    run_mainloop<PW1, 8>(smbase, TA1, TB1, 2 * TA1, wrow, nt0, lane, acc);
    __syncthreads();

    {   // h1 = relu(acc+b1) -> restage as KD=64 tiles (overlay)
        const int rA = lane >> 2, kq = lane & 3;
        const int rlo = wrow + rA, rhi = rlo + 8;
#pragma unroll
        for (int nt = 0; nt < 4; nt++) {
            int col = (nt0 + nt) * 8 + kq * 2;
            float v0x = fmaxf(acc[nt][0] + bsh1[col], 0.f);
            float v0y = fmaxf(acc[nt][1] + bsh1[col + 1], 0.f);
            float v1x = fmaxf(acc[nt][2] + bsh1[col], 0.f);
            float v1y = fmaxf(acc[nt][3] + bsh1[col + 1], 0.f);
            int w = col >> 1;
            uint32_t h0, l0, h1, l1;
            split2(v0x, v0y, h0, l0);
            split2(v1x, v1y, h1, l1);
            sm[rlo * PW2 + w]       = h0;
            sm[TA2 + rlo * PW2 + w] = l0;
            sm[rhi * PW2 + w]       = h1;
            sm[TA2 + rhi * PW2 + w] = l1;
        }
    }
    for (int q = tid; q < 64 * 16; q += 512) {
        int r = q >> 4, c = (q & 15) * 4;
        float4 v = *(const float4*)(W2 + (long)r * 64 + c);
        split4store(sm + 2 * TA2, sm + 2 * TA2 + TB2, r * PW2 + (c >> 1), v);
    }
    __syncthreads();

    float acc2[4][4];
#pragma unroll
    for (int nt = 0; nt < 4; nt++)
#pragma unroll
        for (int j = 0; j < 4; j++) acc2[nt][j] = 0.f;
    run_mainloop<PW2, 4>(smbase, TA2, TB2, 2 * TA2, wrow, nt0, lane, acc2);

    const int rA = lane >> 2, kq = lane & 3;
    const long r_lo = row0 + wrow + rA, r_hi = r_lo + 8;
#pragma unroll
    for (int nt = 0; nt < 4; nt++) {
        int col = (nt0 + nt) * 8 + kq * 2;
        float2 v0 = make_float2(fmaxf(acc2[nt][0] + bsh2[col], 0.f),
                                fmaxf(acc2[nt][1] + bsh2[col + 1], 0.f));
        float2 v1 = make_float2(fmaxf(acc2[nt][2] + bsh2[col], 0.f),
                                fmaxf(acc2[nt][3] + bsh2[col + 1], 0.f));
        if (r_lo < NN) *(float2*)(out + r_lo * 64 + col) = v0;
        if (r_hi < NN) *(float2*)(out + r_hi * 64 + col) = v1;
    }
}

// =========== fused back MLP + head ===========
__global__ void __launch_bounds__(512) mlp_back_kernel(const float* __restrict__ X,
                                                       const float* __restrict__ W3,
                                                       const float* __restrict__ b3,
                                                       const float* __restrict__ W4,
                                                       const float* __restrict__ b4,
                                                       float* __restrict__ out) {
    constexpr int PW = 36, TA = 128 * PW, TB = 64 * PW;
    extern __shared__ uint32_t sm[];
    __shared__ float bsh[64], W4sh[128], b4sh[2];
    __shared__ float hp[2][128][2];

    const int tid = threadIdx.x;
    const long row0 = (long)blockIdx.x * 128;
    if (tid < 64)  bsh[tid] = b3[tid];
    if (tid < 128) W4sh[tid] = W4[tid];
    if (tid < 2)   b4sh[tid] = b4[tid];

    for (int q = tid; q < 128 * 16; q += 512) {
        int r = q >> 4, c = (q & 15) * 4;
        long gr = row0 + r; if (gr >= NN) gr = NN - 1;
        float4 v = *(const float4*)(X + gr * 64 + c);
        split4store(sm, sm + TA, r * PW + (c >> 1), v);
    }
    for (int q = tid; q < 64 * 16; q += 512) {
        int r = q >> 4, c = (q & 15) * 4;
        float4 v = *(const float4*)(W3 + (long)r * 64 + c);
        split4store(sm + 2 * TA, sm + 2 * TA + TB, r * PW + (c >> 1), v);
    }
    __syncthreads();

    const int warp = tid >> 5, lane = tid & 31;
    const int wrow = (warp & 7) * 16;
    const int nt0w = warp >> 3;
    const int nt0 = nt0w * 4;
    const uint32_t smbase = (uint32_t)__cvta_generic_to_shared(sm);

    float acc[4][4];
#pragma unroll
    for (int nt = 0; nt < 4; nt++)
#pragma unroll
        for (int j = 0; j < 4; j++) acc[nt][j] = 0.f;
    run_mainloop<PW, 4>(smbase, TA, TB, 2 * TA, wrow, nt0, lane, acc);

    const int rA = lane >> 2, kq = lane & 3;
    float p00 = 0.f, p01 = 0.f, p10 = 0.f, p11 = 0.f;
#pragma unroll
    for (int nt = 0; nt < 4; nt++) {
        int c = (nt0 + nt) * 8 + kq * 2;
        float v0x = fmaxf(acc[nt][0] + bsh[c], 0.f);
        float v0y = fmaxf(acc[nt][1] + bsh[c + 1], 0.f);
        float v1x = fmaxf(acc[nt][2] + bsh[c], 0.f);
        float v1y = fmaxf(acc[nt][3] + bsh[c + 1], 0.f);
        float w0a = W4sh[c], w0b = W4sh[c + 1];
        float w1a = W4sh[64 + c], w1b = W4sh[64 + c + 1];
        p00 = fmaf(v0x, w0a, fmaf(v0y, w0b, p00));
        p01 = fmaf(v0x, w1a, fmaf(v0y, w1b, p01));
        p10 = fmaf(v1x, w0a, fmaf(v1y, w0b, p10));
        p11 = fmaf(v1x, w1a, fmaf(v1y, w1b, p11));
    }
    p00 += __shfl_xor_sync(0xffffffffu, p00, 1); p00 += __shfl_xor_sync(0xffffffffu, p00, 2);
    p01 += __shfl_xor_sync(0xffffffffu, p01, 1); p01 += __shfl_xor_sync(0xffffffffu, p01, 2);
    p10 += __shfl_xor_sync(0xffffffffu, p10, 1); p10 += __shfl_xor_sync(0xffffffffu, p10, 2);
    p11 += __shfl_xor_sync(0xffffffffu, p11, 1); p11 += __shfl_xor_sync(0xffffffffu, p11, 2);
    if (kq == 0) {
        hp[nt0w][wrow + rA][0] = p00;
        hp[nt0w][wrow + rA][1] = p01;
        hp[nt0w][wrow + rA + 8][0] = p10;
        hp[nt0w][wrow + rA + 8][1] = p11;
    }
    __syncthreads();
    if (tid < 256) {
        int row = tid >> 1, cls = tid & 1;
        long gr = row0 + row;
        if (gr < NN) out[gr * 2 + cls] = hp[0][row][cls] + hp[1][row][cls] + b4sh[cls];
    }
}

// ------------- normalized SpMM: Sout[n,:] = dinv[n] * sum_{e: dst=n} dinv[s]*Xin[s,:] -------------
// Warp per node; half-warp per neighbor-parity, float4 per lane (LDG.128).
// Per iteration: 8 neighbors (4 per half), 4 independent float4 chains per lane.
__global__ void __launch_bounds__(256) spmm_norm_kernel(const float* __restrict__ Xin,
                                                        float* __restrict__ Sout) {
    int n = (blockIdx.x * 256 + threadIdx.x) >> 5;
    if (n >= NN) return;
    const int lane = threadIdx.x & 31;
    const int half = lane >> 4;           // 0: even neighbors, 1: odd neighbors
    const int l16 = lane & 15;
    int cnt = g_cnt[n];
    if (cnt > BCAP) cnt = BCAP;
    const int* bk = &g_bucket[(size_t)n * BCAP];
    const float* xb = Xin + (size_t)l16 * 4;

    float4 a0 = make_float4(0.f, 0.f, 0.f, 0.f);
    float4 a1 = a0, a2 = a0, a3 = a0;

    int i = 0;
    for (; i + 7 < cnt; i += 8) {
        int4 p = *(const int4*)(bk + i);
        int4 q = *(const int4*)(bk + i + 4);
        int s0 = half ? p.y : p.x;
        int s1 = half ? p.w : p.z;
        int s2 = half ? q.y : q.x;
        int s3 = half ? q.w : q.z;
        float d0 = g_dinv[s0], d1 = g_dinv[s1], d2 = g_dinv[s2], d3 = g_dinv[s3];
        float4 v0 = *(const float4*)(xb + (size_t)s0 * 64);
        float4 v1 = *(const float4*)(xb + (size_t)s1 * 64);
        float4 v2 = *(const float4*)(xb + (size_t)s2 * 64);
        float4 v3 = *(const float4*)(xb + (size_t)s3 * 64);
        a0.x = fmaf(v0.x, d0, a0.x); a0.y = fmaf(v0.y, d0, a0.y);
        a0.z = fmaf(v0.z, d0, a0.z); a0.w = fmaf(v0.w, d0, a0.w);
        a1.x = fmaf(v1.x, d1, a1.x); a1.y = fmaf(v1.y, d1, a1.y);
        a1.z = fmaf(v1.z, d1, a1.z); a1.w = fmaf(v1.w, d1, a1.w);
        a2.x = fmaf(v2.x, d2, a2.x); a2.y = fmaf(v2.y, d2, a2.y);
        a2.z = fmaf(v2.z, d2, a2.z); a2.w = fmaf(v2.w, d2, a2.w);
        a3.x = fmaf(v3.x, d3, a3.x); a3.y = fmaf(v3.y, d3, a3.y);
        a3.z = fmaf(v3.z, d3, a3.z); a3.w = fmaf(v3.w, d3, a3.w);
    }
    // pair tail: both halves take neighbor i+half
    for (; i + 1 < cnt; i += 2) {
        int s = bk[i + half];
        float ds = g_dinv[s];
        float4 v = *(const float4*)(xb + (size_t)s * 64);
        a0.x = fmaf(v.x, ds, a0.x); a0.y = fmaf(v.y, ds, a0.y);
        a0.z = fmaf(v.z, ds, a0.z); a0.w = fmaf(v.w, ds, a0.w);
    }
    // final odd neighbor: half 0 only
    if (i < cnt && half == 0) {
        int s = bk[i];
        float ds = g_dinv[s];
        float4 v = *(const float4*)(xb + (size_t)s * 64);
        a0.x = fmaf(v.x, ds, a0.x); a0.y = fmaf(v.y, ds, a0.y);
        a0.z = fmaf(v.z, ds, a0.z); a0.w = fmaf(v.w, ds, a0.w);
    }

    float4 t;
    t.x = (a0.x + a1.x) + (a2.x + a3.x);
    t.y = (a0.y + a1.y) + (a2.y + a3.y);
    t.z = (a0.z + a1.z) + (a2.z + a3.z);
    t.w = (a0.w + a1.w) + (a2.w + a3.w);
    // cross-half combine
    t.x += __shfl_xor_sync(0xffffffffu, t.x, 16);
    t.y += __shfl_xor_sync(0xffffffffu, t.y, 16);
    t.z += __shfl_xor_sync(0xffffffffu, t.z, 16);
    t.w += __shfl_xor_sync(0xffffffffu, t.w, 16);

    if (half == 0) {
        float dn = g_dinv[n];
        t.x *= dn; t.y *= dn; t.z *= dn; t.w *= dn;
        *(float4*)(Sout + (size_t)n * 64 + l16 * 4) = t;
    }
}

// ---------------- launch ----------------
extern "C" void kernel_launch(void* const* d_in, const int* in_sizes, int n_in,
                              void* d_out, int out_size) {
    const float* in_feat = (const float*)d_in[0];
    const int*   src     = (const int*)d_in[1];
    const int*   dst     = (const int*)d_in[2];
    const float* W1  = (const float*)d_in[3];
    const float* b1  = (const float*)d_in[4];
    const float* W2  = (const float*)d_in[5];
    const float* b2  = (const float*)d_in[6];
    const float* Wc1 = (const float*)d_in[7];
    const float* bc1 = (const float*)d_in[8];
    const float* Wc2 = (const float*)d_in[9];
    const float* bc2 = (const float*)d_in[10];
    const float* W3  = (const float*)d_in[11];
    const float* b3  = (const float*)d_in[12];
    const float* W4  = (const float*)d_in[13];
    const float* b4  = (const float*)d_in[14];
    float* out = (float*)d_out;

    float *h2, *S1, *S2, *c1, *c2;
    int* cnt;
    cudaGetSymbolAddress((void**)&h2, g_h2);
    cudaGetSymbolAddress((void**)&S1, g_S1);
    cudaGetSymbolAddress((void**)&S2, g_S2);
    cudaGetSymbolAddress((void**)&c1, g_c1);
    cudaGetSymbolAddress((void**)&c2, g_c2);
    cudaGetSymbolAddress((void**)&cnt, g_cnt);

    const int FRONT_SMEM = (2 * 128 * 68 + 2 * 64 * 68) * 4;   // 104448
    const int BACK_SMEM  = (2 * 128 * 36 + 2 * 64 * 36) * 4;   // 55296
    const int CAT_SMEM   = (2 * 128 * 52 + 2 * 64 * 52) * 4;   // 79872

    cudaFuncSetAttribute(front_build_kernel, cudaFuncAttributeMaxDynamicSharedMemorySize, FRONT_SMEM);
    cudaFuncSetAttribute(mlp_back_kernel,    cudaFuncAttributeMaxDynamicSharedMemorySize, BACK_SMEM);
    cudaFuncSetAttribute(gemm_mma_kernel<192, 96, 1>, cudaFuncAttributeMaxDynamicSharedMemorySize, CAT_SMEM);

    const int GN = (NN + 255) / 256;
    const int GW = (NN * 32 + 255) / 256;

    // zero counts, then fused front-MLP || bucket-build
    cudaMemsetAsync(cnt, 0, NN * sizeof(int));
    front_build_kernel<<<GT + GB, 512, FRONT_SMEM>>>(in_feat, W1, b1, W2, b2, h2, src, dst);
    dinv_kernel<<<GN, 256>>>();

    // ChebConv 1
    spmm_norm_kernel<<<GW, 256>>>(h2, S1);
    spmm_norm_kernel<<<GW, 256>>>(S1, S2);
    gemm_mma_kernel<192, 96, 1><<<GT, 512, CAT_SMEM>>>(h2, S1, S2, Wc1, bc1, c1, 1);

    // ChebConv 2
    spmm_norm_kernel<<<GW, 256>>>(c1, S1);
    spmm_norm_kernel<<<GW, 256>>>(S1, S2);
    gemm_mma_kernel<192, 96, 1><<<GT, 512, CAT_SMEM>>>(c1, S1, S2, Wc2, bc2, c2, 1);

    // fused back MLP + head
    mlp_back_kernel<<<GT, 512, BACK_SMEM>>>(c2, W3, b3, W4, b4, out);
}

// round 14
// speedup vs baseline: 1.0971x; 1.0971x over previous
#include <cuda_runtime.h>
#include <cuda_bf16.h>
#include <cstdint>

#define NN 50000
#define EE 800000
#define BCAP 64           // max in-degree ~38 (Binomial mean 16, sigma 4); 64 is >6-sigma safe
#define GT 391            // 128-row GEMM CTAs
#define GB 1563           // bucket-build blocks (512 edges each)

// ---------------- scratch (static device globals; no allocation) ----------------
__device__ int   g_cnt[NN];
__device__ int   g_bucket[(size_t)NN * BCAP];
__device__ float g_dinv[NN];
__device__ float g_h2 [(size_t)NN * 64];
__device__ float g_S1 [(size_t)NN * 64];
__device__ float g_S2 [(size_t)NN * 64];
__device__ float g_c1 [(size_t)NN * 64];
__device__ float g_c2 [(size_t)NN * 64];

__device__ __forceinline__ uint32_t pack_bf16(float a, float b) {
    __nv_bfloat162 t = __floats2bfloat162_rn(a, b);
    return *reinterpret_cast<uint32_t*>(&t);
}

__device__ __forceinline__ void split2(float a, float b, uint32_t& hi, uint32_t& lo) {
    __nv_bfloat16 ah = __float2bfloat16(a), bh = __float2bfloat16(b);
    __nv_bfloat162 hv; hv.x = ah; hv.y = bh;
    hi = *reinterpret_cast<uint32_t*>(&hv);
    lo = pack_bf16(a - __bfloat162float(ah), b - __bfloat162float(bh));
}

__device__ __forceinline__ void split4store(uint32_t* Hi, uint32_t* Lo, int w, float4 v) {
    uint32_t h0, l0, h1, l1;
    split2(v.x, v.y, h0, l0);
    split2(v.z, v.w, h1, l1);
    Hi[w] = h0; Hi[w + 1] = h1;
    Lo[w] = l0; Lo[w + 1] = l1;
}

__device__ __forceinline__ void mma16816(float* c, const uint32_t* a, uint32_t b0, uint32_t b1) {
    asm volatile(
        "mma.sync.aligned.m16n8k16.row.col.f32.bf16.bf16.f32 "
        "{%0,%1,%2,%3}, {%4,%5,%6,%7}, {%8,%9}, {%0,%1,%2,%3};"
        : "+f"(c[0]), "+f"(c[1]), "+f"(c[2]), "+f"(c[3])
        : "r"(a[0]), "r"(a[1]), "r"(a[2]), "r"(a[3]), "r"(b0), "r"(b1));
}

__device__ __forceinline__ void ldsm_x4(uint32_t addr, uint32_t* r) {
    asm volatile("ldmatrix.sync.aligned.m8n8.x4.shared.b16 {%0,%1,%2,%3}, [%4];"
                 : "=r"(r[0]), "=r"(r[1]), "=r"(r[2]), "=r"(r[3]) : "r"(addr));
}
__device__ __forceinline__ void ldsm_x2(uint32_t addr, uint32_t* r) {
    asm volatile("ldmatrix.sync.aligned.m8n8.x2.shared.b16 {%0,%1}, [%2];"
                 : "=r"(r[0]), "=r"(r[1]) : "r"(addr));
}

// 3-term bf16 split mainloop; PW/4 must be odd for conflict-free LDSM.
template <int PW, int NK>
__device__ __forceinline__ void run_mainloop(uint32_t smbase, int TA_w, int TB_w,
                                             int baseB_w, int wrow, int nt0,
                                             int lane, float acc[4][4]) {
    const int mA = lane >> 3;
    const uint32_t aH = smbase + (((wrow + (lane & 7) + (mA & 1) * 8) * PW + (mA >> 1) * 4) << 2);
    const uint32_t aL = aH + (TA_w << 2);
    const int l15 = lane & 15;
    uint32_t bH[4], bL[4];
#pragma unroll
    for (int nt = 0; nt < 4; nt++) {
        bH[nt] = smbase + ((baseB_w + ((nt0 + nt) * 8 + (l15 & 7)) * PW + (l15 >> 3) * 4) << 2);
        bL[nt] = bH[nt] + (TB_w << 2);
    }
#pragma unroll
    for (int ks = 0; ks < NK; ks++) {
        const uint32_t kb = (uint32_t)ks * 32;
        uint32_t ah[4], al[4];
        ldsm_x4(aH + kb, ah);
        ldsm_x4(aL + kb, al);
#pragma unroll
        for (int nt = 0; nt < 4; nt++) {
            uint32_t bh[2], bl[2];
            ldsm_x2(bH[nt] + kb, bh);
            ldsm_x2(bL[nt] + kb, bl);
            mma16816(acc[nt], ah, bh[0], bh[1]);
            mma16816(acc[nt], al, bh[0], bh[1]);
            mma16816(acc[nt], ah, bl[0], bl[1]);
        }
    }
}

__global__ void dinv_kernel() {
    int i = blockIdx.x * 256 + threadIdx.x;
    if (i >= NN) return;
    int c = g_cnt[i];
    float d = (float)(c > 0 ? c : 1);
    g_dinv[i] = rsqrtf(d);
}

// =========== K-chunked cat-GEMM: out = relu([h|-S1|2S2-h] @ W[64,192]^T + b) =========
template <int KD, int KC, int CAT>
__global__ void __launch_bounds__(512) gemm_mma_kernel(const float* __restrict__ X,
                                                       const float* __restrict__ S1,
                                                       const float* __restrict__ S2,
                                                       const float* __restrict__ W,
                                                       const float* __restrict__ bias,
                                                       float* __restrict__ out,
                                                       int do_relu) {
    constexpr int PW = KC / 2 + 4;
    constexpr int TA = 128 * PW, TB = 64 * PW;
    constexpr int NCH = KD / KC, NK = KC / 16, KQ = KC / 4;
    extern __shared__ uint32_t sm[];
    __shared__ float bsh[64];

    const int tid = threadIdx.x;
    const long row0 = (long)blockIdx.x * 128;
    if (tid < 64) bsh[tid] = bias[tid];

    const int warp = tid >> 5, lane = tid & 31;
    const int wrow = (warp & 7) * 16;
    const int nt0 = (warp >> 3) * 4;
    const uint32_t smbase = (uint32_t)__cvta_generic_to_shared(sm);

    float acc[4][4];
#pragma unroll
    for (int nt = 0; nt < 4; nt++)
#pragma unroll
        for (int j = 0; j < 4; j++) acc[nt][j] = 0.f;

#pragma unroll
    for (int ch = 0; ch < NCH; ch++) {
        if (ch) __syncthreads();
        for (int q = tid; q < 128 * KQ; q += 512) {
            int r = q / KQ, cl = (q % KQ) * 4, gc = ch * KC + cl;
            long gr = row0 + r; if (gr >= NN) gr = NN - 1;
            float4 v;
            if (CAT) {
                if (gc < 64) {
                    v = *(const float4*)(X + gr * 64 + gc);
                } else if (gc < 128) {
                    float4 s = *(const float4*)(S1 + gr * 64 + (gc - 64));
                    v = make_float4(-s.x, -s.y, -s.z, -s.w);
                } else {
                    float4 s = *(const float4*)(S2 + gr * 64 + (gc - 128));
                    float4 h = *(const float4*)(X + gr * 64 + (gc - 128));
                    v = make_float4(fmaf(2.f, s.x, -h.x), fmaf(2.f, s.y, -h.y),
                                    fmaf(2.f, s.z, -h.z), fmaf(2.f, s.w, -h.w));
                }
            } else {
                v = *(const float4*)(X + gr * KD + gc);
            }
            split4store(sm, sm + TA, r * PW + (cl >> 1), v);
        }
        for (int q = tid; q < 64 * KQ; q += 512) {
            int r = q / KQ, cl = (q % KQ) * 4, gc = ch * KC + cl;
            float4 v = *(const float4*)(W + (long)r * KD + gc);
            split4store(sm + 2 * TA, sm + 2 * TA + TB, r * PW + (cl >> 1), v);
        }
        __syncthreads();
        run_mainloop<PW, NK>(smbase, TA, TB, 2 * TA, wrow, nt0, lane, acc);
    }

    const int rA = lane >> 2, kq = lane & 3;
    const long r_lo = row0 + wrow + rA, r_hi = r_lo + 8;
#pragma unroll
    for (int nt = 0; nt < 4; nt++) {
        int col = (nt0 + nt) * 8 + kq * 2;
        float2 v0 = make_float2(acc[nt][0] + bsh[col], acc[nt][1] + bsh[col + 1]);
        float2 v1 = make_float2(acc[nt][2] + bsh[col], acc[nt][3] + bsh[col + 1]);
        if (do_relu) {
            v0.x = fmaxf(v0.x, 0.f); v0.y = fmaxf(v0.y, 0.f);
            v1.x = fmaxf(v1.x, 0.f); v1.y = fmaxf(v1.y, 0.f);
        }
        if (r_lo < NN) *(float2*)(out + r_lo * 64 + col) = v0;
        if (r_hi < NN) *(float2*)(out + r_hi * 64 + col) = v1;
    }
}

// =========== fused front MLP + bucket build ===========
__global__ void __launch_bounds__(512) front_build_kernel(const float* __restrict__ X,
                                                          const float* __restrict__ W1,
                                                          const float* __restrict__ b1,
                                                          const float* __restrict__ W2,
                                                          const float* __restrict__ b2,
                                                          float* __restrict__ out,
                                                          const int* __restrict__ src,
                                                          const int* __restrict__ dst) {
    extern __shared__ uint32_t sm[];
    const int b = blockIdx.x;
    const int tid = threadIdx.x;

    if (b >= GT) {                               // bucket build
        int e = (b - GT) * 512 + tid;
        if (e < EE) {
            int d = dst[e];
            int p = atomicAdd(&g_cnt[d], 1);
            if (p < BCAP) g_bucket[(size_t)d * BCAP + p] = src[e];
        }
        return;
    }

    constexpr int PW1 = 68, TA1 = 128 * PW1, TB1 = 64 * PW1;
    constexpr int PW2 = 36, TA2 = 128 * PW2, TB2 = 64 * PW2;
    __shared__ float bsh1[64], bsh2[64];
    const long row0 = (long)b * 128;
    if (tid < 64) { bsh1[tid] = b1[tid]; bsh2[tid] = b2[tid]; }

    for (int q = tid; q < 128 * 32; q += 512) {
        int r = q >> 5, c = (q & 31) * 4;
        long gr = row0 + r; if (gr >= NN) gr = NN - 1;
        float4 v = *(const float4*)(X + gr * 128 + c);
        split4store(sm, sm + TA1, r * PW1 + (c >> 1), v);
    }
    for (int q = tid; q < 64 * 32; q += 512) {
        int r = q >> 5, c = (q & 31) * 4;
        float4 v = *(const float4*)(W1 + (long)r * 128 + c);
        split4store(sm + 2 * TA1, sm + 2 * TA1 + TB1, r * PW1 + (c >> 1), v);
    }
    __syncthreads();

    const int warp = tid >> 5, lane = tid & 31;
    const int wrow = (warp & 7) * 16;
    const int nt0 = (warp >> 3) * 4;
    const uint32_t smbase = (uint32_t)__cvta_generic_to_shared(sm);

    float acc[4][4];
#pragma unroll
    for (int nt = 0; nt < 4; nt++)
#pragma unroll
        for (int j = 0; j < 4; j++) acc[nt][j] = 0.f;
    run_mainloop<PW1, 8>(smbase, TA1, TB1, 2 * TA1, wrow, nt0, lane, acc);
    __syncthreads();

    {   // h1 = relu(acc+b1) -> restage as KD=64 tiles (overlay)
        const int rA = lane >> 2, kq = lane & 3;
        const int rlo = wrow + rA, rhi = rlo + 8;
#pragma unroll
        for (int nt = 0; nt < 4; nt++) {
            int col = (nt0 + nt) * 8 + kq * 2;
            float v0x = fmaxf(acc[nt][0] + bsh1[col], 0.f);
            float v0y = fmaxf(acc[nt][1] + bsh1[col + 1], 0.f);
            float v1x = fmaxf(acc[nt][2] + bsh1[col], 0.f);
            float v1y = fmaxf(acc[nt][3] + bsh1[col + 1], 0.f);
            int w = col >> 1;
            uint32_t h0, l0, h1, l1;
            split2(v0x, v0y, h0, l0);
            split2(v1x, v1y, h1, l1);
            sm[rlo * PW2 + w]       = h0;
            sm[TA2 + rlo * PW2 + w] = l0;
            sm[rhi * PW2 + w]       = h1;
            sm[TA2 + rhi * PW2 + w] = l1;
        }
    }
    for (int q = tid; q < 64 * 16; q += 512) {
        int r = q >> 4, c = (q & 15) * 4;
        float4 v = *(const float4*)(W2 + (long)r * 64 + c);
        split4store(sm + 2 * TA2, sm + 2 * TA2 + TB2, r * PW2 + (c >> 1), v);
    }
    __syncthreads();

    float acc2[4][4];
#pragma unroll
    for (int nt = 0; nt < 4; nt++)
#pragma unroll
        for (int j = 0; j < 4; j++) acc2[nt][j] = 0.f;
    run_mainloop<PW2, 4>(smbase, TA2, TB2, 2 * TA2, wrow, nt0, lane, acc2);

    const int rA = lane >> 2, kq = lane & 3;
    const long r_lo = row0 + wrow + rA, r_hi = r_lo + 8;
#pragma unroll
    for (int nt = 0; nt < 4; nt++) {
        int col = (nt0 + nt) * 8 + kq * 2;
        float2 v0 = make_float2(fmaxf(acc2[nt][0] + bsh2[col], 0.f),
                                fmaxf(acc2[nt][1] + bsh2[col + 1], 0.f));
        float2 v1 = make_float2(fmaxf(acc2[nt][2] + bsh2[col], 0.f),
                                fmaxf(acc2[nt][3] + bsh2[col + 1], 0.f));
        if (r_lo < NN) *(float2*)(out + r_lo * 64 + col) = v0;
        if (r_hi < NN) *(float2*)(out + r_hi * 64 + col) = v1;
    }
}

// =========== fused back MLP + head ===========
__global__ void __launch_bounds__(512) mlp_back_kernel(const float* __restrict__ X,
                                                       const float* __restrict__ W3,
                                                       const float* __restrict__ b3,
                                                       const float* __restrict__ W4,
                                                       const float* __restrict__ b4,
                                                       float* __restrict__ out) {
    constexpr int PW = 36, TA = 128 * PW, TB = 64 * PW;
    extern __shared__ uint32_t sm[];
    __shared__ float bsh[64], W4sh[128], b4sh[2];
    __shared__ float hp[2][128][2];

    const int tid = threadIdx.x;
    const long row0 = (long)blockIdx.x * 128;
    if (tid < 64)  bsh[tid] = b3[tid];
    if (tid < 128) W4sh[tid] = W4[tid];
    if (tid < 2)   b4sh[tid] = b4[tid];

    for (int q = tid; q < 128 * 16; q += 512) {
        int r = q >> 4, c = (q & 15) * 4;
        long gr = row0 + r; if (gr >= NN) gr = NN - 1;
        float4 v = *(const float4*)(X + gr * 64 + c);
        split4store(sm, sm + TA, r * PW + (c >> 1), v);
    }
    for (int q = tid; q < 64 * 16; q += 512) {
        int r = q >> 4, c = (q & 15) * 4;
        float4 v = *(const float4*)(W3 + (long)r * 64 + c);
        split4store(sm + 2 * TA, sm + 2 * TA + TB, r * PW + (c >> 1), v);
    }
    __syncthreads();

    const int warp = tid >> 5, lane = tid & 31;
    const int wrow = (warp & 7) * 16;
    const int nt0w = warp >> 3;
    const int nt0 = nt0w * 4;
    const uint32_t smbase = (uint32_t)__cvta_generic_to_shared(sm);

    float acc[4][4];
#pragma unroll
    for (int nt = 0; nt < 4; nt++)
#pragma unroll
        for (int j = 0; j < 4; j++) acc[nt][j] = 0.f;
    run_mainloop<PW, 4>(smbase, TA, TB, 2 * TA, wrow, nt0, lane, acc);

    const int rA = lane >> 2, kq = lane & 3;
    float p00 = 0.f, p01 = 0.f, p10 = 0.f, p11 = 0.f;
#pragma unroll
    for (int nt = 0; nt < 4; nt++) {
        int c = (nt0 + nt) * 8 + kq * 2;
        float v0x = fmaxf(acc[nt][0] + bsh[c], 0.f);
        float v0y = fmaxf(acc[nt][1] + bsh[c + 1], 0.f);
        float v1x = fmaxf(acc[nt][2] + bsh[c], 0.f);
        float v1y = fmaxf(acc[nt][3] + bsh[c + 1], 0.f);
        float w0a = W4sh[c], w0b = W4sh[c + 1];
        float w1a = W4sh[64 + c], w1b = W4sh[64 + c + 1];
        p00 = fmaf(v0x, w0a, fmaf(v0y, w0b, p00));
        p01 = fmaf(v0x, w1a, fmaf(v0y, w1b, p01));
        p10 = fmaf(v1x, w0a, fmaf(v1y, w0b, p10));
        p11 = fmaf(v1x, w1a, fmaf(v1y, w1b, p11));
    }
    p00 += __shfl_xor_sync(0xffffffffu, p00, 1); p00 += __shfl_xor_sync(0xffffffffu, p00, 2);
    p01 += __shfl_xor_sync(0xffffffffu, p01, 1); p01 += __shfl_xor_sync(0xffffffffu, p01, 2);
    p10 += __shfl_xor_sync(0xffffffffu, p10, 1); p10 += __shfl_xor_sync(0xffffffffu, p10, 2);
    p11 += __shfl_xor_sync(0xffffffffu, p11, 1); p11 += __shfl_xor_sync(0xffffffffu, p11, 2);
    if (kq == 0) {
        hp[nt0w][wrow + rA][0] = p00;
        hp[nt0w][wrow + rA][1] = p01;
        hp[nt0w][wrow + rA + 8][0] = p10;
        hp[nt0w][wrow + rA + 8][1] = p11;
    }
    __syncthreads();
    if (tid < 256) {
        int row = tid >> 1, cls = tid & 1;
        long gr = row0 + row;
        if (gr < NN) out[gr * 2 + cls] = hp[0][row][cls] + hp[1][row][cls] + b4sh[cls];
    }
}

// ------------- normalized SpMM: Sout[n,:] = dinv[n] * sum_{e: dst=n} dinv[s]*Xin[s,:] -------------
// Warp per node; int4 bucket loads software-pipelined one iteration ahead;
// 4 independent float2 accumulator chains (round-12 shape, 32 regs).
__global__ void __launch_bounds__(256) spmm_norm_kernel(const float* __restrict__ Xin,
                                                        float* __restrict__ Sout) {
    int n = (blockIdx.x * 256 + threadIdx.x) >> 5;
    if (n >= NN) return;
    int lane = threadIdx.x & 31;
    int cnt = g_cnt[n];
    if (cnt > BCAP) cnt = BCAP;
    const int4* bk4 = (const int4*)&g_bucket[(size_t)n * BCAP];
    const float* xb = Xin + (size_t)lane * 2;
    float2 a0 = make_float2(0.f, 0.f), a1 = make_float2(0.f, 0.f);
    float2 a2 = make_float2(0.f, 0.f), a3 = make_float2(0.f, 0.f);

    int i = 0;
    if (i + 3 < cnt) {
        int4 s4 = bk4[0];
        for (; i + 3 < cnt; i += 4) {
            // prefetch next indices before the dependent gathers
            int4 nxt = (i + 7 < cnt) ? bk4[(i >> 2) + 1] : s4;
            float d0 = g_dinv[s4.x], d1 = g_dinv[s4.y], d2 = g_dinv[s4.z], d3 = g_dinv[s4.w];
            float2 v0 = *(const float2*)(xb + (size_t)s4.x * 64);
            float2 v1 = *(const float2*)(xb + (size_t)s4.y * 64);
            float2 v2 = *(const float2*)(xb + (size_t)s4.z * 64);
            float2 v3 = *(const float2*)(xb + (size_t)s4.w * 64);
            a0.x = fmaf(v0.x, d0, a0.x); a0.y = fmaf(v0.y, d0, a0.y);
            a1.x = fmaf(v1.x, d1, a1.x); a1.y = fmaf(v1.y, d1, a1.y);
            a2.x = fmaf(v2.x, d2, a2.x); a2.y = fmaf(v2.y, d2, a2.y);
            a3.x = fmaf(v3.x, d3, a3.x); a3.y = fmaf(v3.y, d3, a3.y);
            s4 = nxt;
        }
    }
    const int* bk = (const int*)bk4;
    for (; i < cnt; i++) {
        int s = bk[i];
        float ds = g_dinv[s];
        float2 v = *(const float2*)(xb + (size_t)s * 64);
        a0.x = fmaf(v.x, ds, a0.x); a0.y = fmaf(v.y, ds, a0.y);
    }
    float dn = g_dinv[n];
    float2 acc;
    acc.x = ((a0.x + a1.x) + (a2.x + a3.x)) * dn;
    acc.y = ((a0.y + a1.y) + (a2.y + a3.y)) * dn;
    *(float2*)(Sout + (size_t)n * 64 + lane * 2) = acc;
}

// ---------------- launch ----------------
extern "C" void kernel_launch(void* const* d_in, const int* in_sizes, int n_in,
                              void* d_out, int out_size) {
    const float* in_feat = (const float*)d_in[0];
    const int*   src     = (const int*)d_in[1];
    const int*   dst     = (const int*)d_in[2];
    const float* W1  = (const float*)d_in[3];
    const float* b1  = (const float*)d_in[4];
    const float* W2  = (const float*)d_in[5];
    const float* b2  = (const float*)d_in[6];
    const float* Wc1 = (const float*)d_in[7];
    const float* bc1 = (const float*)d_in[8];
    const float* Wc2 = (const float*)d_in[9];
    const float* bc2 = (const float*)d_in[10];
    const float* W3  = (const float*)d_in[11];
    const float* b3  = (const float*)d_in[12];
    const float* W4  = (const float*)d_in[13];
    const float* b4  = (const float*)d_in[14];
    float* out = (float*)d_out;

    float *h2, *S1, *S2, *c1, *c2;
    int* cnt;
    cudaGetSymbolAddress((void**)&h2, g_h2);
    cudaGetSymbolAddress((void**)&S1, g_S1);
    cudaGetSymbolAddress((void**)&S2, g_S2);
    cudaGetSymbolAddress((void**)&c1, g_c1);
    cudaGetSymbolAddress((void**)&c2, g_c2);
    cudaGetSymbolAddress((void**)&cnt, g_cnt);

    const int FRONT_SMEM = (2 * 128 * 68 + 2 * 64 * 68) * 4;   // 104448
    const int BACK_SMEM  = (2 * 128 * 36 + 2 * 64 * 36) * 4;   // 55296
    const int CAT_SMEM   = (2 * 128 * 52 + 2 * 64 * 52) * 4;   // 79872

    cudaFuncSetAttribute(front_build_kernel, cudaFuncAttributeMaxDynamicSharedMemorySize, FRONT_SMEM);
    cudaFuncSetAttribute(mlp_back_kernel,    cudaFuncAttributeMaxDynamicSharedMemorySize, BACK_SMEM);
    cudaFuncSetAttribute(gemm_mma_kernel<192, 96, 1>, cudaFuncAttributeMaxDynamicSharedMemorySize, CAT_SMEM);

    const int GN = (NN + 255) / 256;
    const int GW = (NN * 32 + 255) / 256;

    // zero counts, then fused front-MLP || bucket-build
    cudaMemsetAsync(cnt, 0, NN * sizeof(int));
    front_build_kernel<<<GT + GB, 512, FRONT_SMEM>>>(in_feat, W1, b1, W2, b2, h2, src, dst);
    dinv_kernel<<<GN, 256>>>();

    // ChebConv 1
    spmm_norm_kernel<<<GW, 256>>>(h2, S1);
    spmm_norm_kernel<<<GW, 256>>>(S1, S2);
    gemm_mma_kernel<192, 96, 1><<<GT, 512, CAT_SMEM>>>(h2, S1, S2, Wc1, bc1, c1, 1);

    // ChebConv 2
    spmm_norm_kernel<<<GW, 256>>>(c1, S1);
    spmm_norm_kernel<<<GW, 256>>>(S1, S2);
    gemm_mma_kernel<192, 96, 1><<<GT, 512, CAT_SMEM>>>(c1, S1, S2, Wc2, bc2, c2, 1);

    // fused back MLP + head
    mlp_back_kernel<<<GT, 512, BACK_SMEM>>>(c2, W3, b3, W4, b4, out);
}

// round 15
// speedup vs baseline: 1.1565x; 1.0542x over previous
#include <cuda_runtime.h>
#include <cuda_bf16.h>
#include <cstdint>

#define NN 50000
#define EE 800000
#define BCAP 64           // max in-degree ~38 (Binomial mean 16, sigma 4); 64 is >6-sigma safe
#define GT 391            // 128-row GEMM CTAs
#define GB 1563           // bucket-build blocks (512 edges each)

// ---------------- scratch (static device globals; no allocation) ----------------
__device__ int   g_cnt[NN];
__device__ int   g_bucket[(size_t)NN * BCAP];
__device__ float g_dinv[NN];
__device__ float g_h2 [(size_t)NN * 64];
__device__ float g_h2s[(size_t)NN * 64];
__device__ float g_S1 [(size_t)NN * 64];
__device__ float g_S1s[(size_t)NN * 64];
__device__ float g_S2 [(size_t)NN * 64];
__device__ float g_c1 [(size_t)NN * 64];
__device__ float g_c1s[(size_t)NN * 64];
__device__ float g_c2 [(size_t)NN * 64];

__device__ __forceinline__ uint32_t pack_bf16(float a, float b) {
    __nv_bfloat162 t = __floats2bfloat162_rn(a, b);
    return *reinterpret_cast<uint32_t*>(&t);
}

__device__ __forceinline__ void split2(float a, float b, uint32_t& hi, uint32_t& lo) {
    __nv_bfloat16 ah = __float2bfloat16(a), bh = __float2bfloat16(b);
    __nv_bfloat162 hv; hv.x = ah; hv.y = bh;
    hi = *reinterpret_cast<uint32_t*>(&hv);
    lo = pack_bf16(a - __bfloat162float(ah), b - __bfloat162float(bh));
}

__device__ __forceinline__ void split4store(uint32_t* Hi, uint32_t* Lo, int w, float4 v) {
    uint32_t h0, l0, h1, l1;
    split2(v.x, v.y, h0, l0);
    split2(v.z, v.w, h1, l1);
    Hi[w] = h0; Hi[w + 1] = h1;
    Lo[w] = l0; Lo[w + 1] = l1;
}

__device__ __forceinline__ void mma16816(float* c, const uint32_t* a, uint32_t b0, uint32_t b1) {
    asm volatile(
        "mma.sync.aligned.m16n8k16.row.col.f32.bf16.bf16.f32 "
        "{%0,%1,%2,%3}, {%4,%5,%6,%7}, {%8,%9}, {%0,%1,%2,%3};"
        : "+f"(c[0]), "+f"(c[1]), "+f"(c[2]), "+f"(c[3])
        : "r"(a[0]), "r"(a[1]), "r"(a[2]), "r"(a[3]), "r"(b0), "r"(b1));
}

__device__ __forceinline__ void ldsm_x4(uint32_t addr, uint32_t* r) {
    asm volatile("ldmatrix.sync.aligned.m8n8.x4.shared.b16 {%0,%1,%2,%3}, [%4];"
                 : "=r"(r[0]), "=r"(r[1]), "=r"(r[2]), "=r"(r[3]) : "r"(addr));
}
__device__ __forceinline__ void ldsm_x2(uint32_t addr, uint32_t* r) {
    asm volatile("ldmatrix.sync.aligned.m8n8.x2.shared.b16 {%0,%1}, [%2];"
                 : "=r"(r[0]), "=r"(r[1]) : "r"(addr));
}

// 3-term bf16 split mainloop; PW/4 must be odd for conflict-free LDSM.
template <int PW, int NK>
__device__ __forceinline__ void run_mainloop(uint32_t smbase, int TA_w, int TB_w,
                                             int baseB_w, int wrow, int nt0,
                                             int lane, float acc[4][4]) {
    const int mA = lane >> 3;
    const uint32_t aH = smbase + (((wrow + (lane & 7) + (mA & 1) * 8) * PW + (mA >> 1) * 4) << 2);
    const uint32_t aL = aH + (TA_w << 2);
    const int l15 = lane & 15;
    uint32_t bH[4], bL[4];
#pragma unroll
    for (int nt = 0; nt < 4; nt++) {
        bH[nt] = smbase + ((baseB_w + ((nt0 + nt) * 8 + (l15 & 7)) * PW + (l15 >> 3) * 4) << 2);
        bL[nt] = bH[nt] + (TB_w << 2);
    }
#pragma unroll
    for (int ks = 0; ks < NK; ks++) {
        const uint32_t kb = (uint32_t)ks * 32;
        uint32_t ah[4], al[4];
        ldsm_x4(aH + kb, ah);
        ldsm_x4(aL + kb, al);
#pragma unroll
        for (int nt = 0; nt < 4; nt++) {
            uint32_t bh[2], bl[2];
            ldsm_x2(bH[nt] + kb, bh);
            ldsm_x2(bL[nt] + kb, bl);
            mma16816(acc[nt], ah, bh[0], bh[1]);
            mma16816(acc[nt], al, bh[0], bh[1]);
            mma16816(acc[nt], ah, bl[0], bl[1]);
        }
    }
}

// ===== dinv + pre-scale: g_dinv[n] = rsqrt(max(cnt,1)); hs = h * dinv (warp/node) =====
__global__ void __launch_bounds__(256) dinv_scale_kernel(const float* __restrict__ h,
                                                         float* __restrict__ hs) {
    int n = (blockIdx.x * 256 + threadIdx.x) >> 5;
    if (n >= NN) return;
    int lane = threadIdx.x & 31;
    int c = g_cnt[n];
    float d = rsqrtf((float)(c > 0 ? c : 1));
    if (lane == 0) g_dinv[n] = d;
    float2 v = *(const float2*)(h + (size_t)n * 64 + lane * 2);
    *(float2*)(hs + (size_t)n * 64 + lane * 2) = make_float2(v.x * d, v.y * d);
}

// =========== K-chunked cat-GEMM: out = relu([h|-S1|2S2-h] @ W[64,192]^T + b) =========
// outs (optional): scaled copy out*dinv[row] for the next spmm hop.
template <int KD, int KC, int CAT>
__global__ void __launch_bounds__(512) gemm_mma_kernel(const float* __restrict__ X,
                                                       const float* __restrict__ S1,
                                                       const float* __restrict__ S2,
                                                       const float* __restrict__ W,
                                                       const float* __restrict__ bias,
                                                       float* __restrict__ out,
                                                       float* __restrict__ outs,
                                                       int do_relu) {
    constexpr int PW = KC / 2 + 4;
    constexpr int TA = 128 * PW, TB = 64 * PW;
    constexpr int NCH = KD / KC, NK = KC / 16, KQ = KC / 4;
    extern __shared__ uint32_t sm[];
    __shared__ float bsh[64];

    const int tid = threadIdx.x;
    const long row0 = (long)blockIdx.x * 128;
    if (tid < 64) bsh[tid] = bias[tid];

    const int warp = tid >> 5, lane = tid & 31;
    const int wrow = (warp & 7) * 16;
    const int nt0 = (warp >> 3) * 4;
    const uint32_t smbase = (uint32_t)__cvta_generic_to_shared(sm);

    float acc[4][4];
#pragma unroll
    for (int nt = 0; nt < 4; nt++)
#pragma unroll
        for (int j = 0; j < 4; j++) acc[nt][j] = 0.f;

#pragma unroll
    for (int ch = 0; ch < NCH; ch++) {
        if (ch) __syncthreads();
        for (int q = tid; q < 128 * KQ; q += 512) {
            int r = q / KQ, cl = (q % KQ) * 4, gc = ch * KC + cl;
            long gr = row0 + r; if (gr >= NN) gr = NN - 1;
            float4 v;
            if (CAT) {
                if (gc < 64) {
                    v = *(const float4*)(X + gr * 64 + gc);
                } else if (gc < 128) {
                    float4 s = *(const float4*)(S1 + gr * 64 + (gc - 64));
                    v = make_float4(-s.x, -s.y, -s.z, -s.w);
                } else {
                    float4 s = *(const float4*)(S2 + gr * 64 + (gc - 128));
                    float4 h = *(const float4*)(X + gr * 64 + (gc - 128));
                    v = make_float4(fmaf(2.f, s.x, -h.x), fmaf(2.f, s.y, -h.y),
                                    fmaf(2.f, s.z, -h.z), fmaf(2.f, s.w, -h.w));
                }
            } else {
                v = *(const float4*)(X + gr * KD + gc);
            }
            split4store(sm, sm + TA, r * PW + (cl >> 1), v);
        }
        for (int q = tid; q < 64 * KQ; q += 512) {
            int r = q / KQ, cl = (q % KQ) * 4, gc = ch * KC + cl;
            float4 v = *(const float4*)(W + (long)r * KD + gc);
            split4store(sm + 2 * TA, sm + 2 * TA + TB, r * PW + (cl >> 1), v);
        }
        __syncthreads();
        run_mainloop<PW, NK>(smbase, TA, TB, 2 * TA, wrow, nt0, lane, acc);
    }

    const int rA = lane >> 2, kq = lane & 3;
    const long r_lo = row0 + wrow + rA, r_hi = r_lo + 8;
    float d_lo = 0.f, d_hi = 0.f;
    if (outs) {
        if (r_lo < NN) d_lo = g_dinv[r_lo];
        if (r_hi < NN) d_hi = g_dinv[r_hi];
    }
#pragma unroll
    for (int nt = 0; nt < 4; nt++) {
        int col = (nt0 + nt) * 8 + kq * 2;
        float2 v0 = make_float2(acc[nt][0] + bsh[col], acc[nt][1] + bsh[col + 1]);
        float2 v1 = make_float2(acc[nt][2] + bsh[col], acc[nt][3] + bsh[col + 1]);
        if (do_relu) {
            v0.x = fmaxf(v0.x, 0.f); v0.y = fmaxf(v0.y, 0.f);
            v1.x = fmaxf(v1.x, 0.f); v1.y = fmaxf(v1.y, 0.f);
        }
        if (r_lo < NN) {
            *(float2*)(out + r_lo * 64 + col) = v0;
            if (outs) *(float2*)(outs + r_lo * 64 + col) = make_float2(v0.x * d_lo, v0.y * d_lo);
        }
        if (r_hi < NN) {
            *(float2*)(out + r_hi * 64 + col) = v1;
            if (outs) *(float2*)(outs + r_hi * 64 + col) = make_float2(v1.x * d_hi, v1.y * d_hi);
        }
    }
}

// =========== fused front MLP + bucket build ===========
__global__ void __launch_bounds__(512) front_build_kernel(const float* __restrict__ X,
                                                          const float* __restrict__ W1,
                                                          const float* __restrict__ b1,
                                                          const float* __restrict__ W2,
                                                          const float* __restrict__ b2,
                                                          float* __restrict__ out,
                                                          const int* __restrict__ src,
                                                          const int* __restrict__ dst) {
    extern __shared__ uint32_t sm[];
    const int b = blockIdx.x;
    const int tid = threadIdx.x;

    if (b >= GT) {                               // bucket build
        int e = (b - GT) * 512 + tid;
        if (e < EE) {
            int d = dst[e];
            int p = atomicAdd(&g_cnt[d], 1);
            if (p < BCAP) g_bucket[(size_t)d * BCAP + p] = src[e];
        }
        return;
    }

    constexpr int PW1 = 68, TA1 = 128 * PW1, TB1 = 64 * PW1;
    constexpr int PW2 = 36, TA2 = 128 * PW2, TB2 = 64 * PW2;
    __shared__ float bsh1[64], bsh2[64];
    const long row0 = (long)b * 128;
    if (tid < 64) { bsh1[tid] = b1[tid]; bsh2[tid] = b2[tid]; }

    for (int q = tid; q < 128 * 32; q += 512) {
        int r = q >> 5, c = (q & 31) * 4;
        long gr = row0 + r; if (gr >= NN) gr = NN - 1;
        float4 v = *(const float4*)(X + gr * 128 + c);
        split4store(sm, sm + TA1, r * PW1 + (c >> 1), v);
    }
    for (int q = tid; q < 64 * 32; q += 512) {
        int r = q >> 5, c = (q & 31) * 4;
        float4 v = *(const float4*)(W1 + (long)r * 128 + c);
        split4store(sm + 2 * TA1, sm + 2 * TA1 + TB1, r * PW1 + (c >> 1), v);
    }
    __syncthreads();

    const int warp = tid >> 5, lane = tid & 31;
    const int wrow = (warp & 7) * 16;
    const int nt0 = (warp >> 3) * 4;
    const uint32_t smbase = (uint32_t)__cvta_generic_to_shared(sm);

    float acc[4][4];
#pragma unroll
    for (int nt = 0; nt < 4; nt++)
#pragma unroll
        for (int j = 0; j < 4; j++) acc[nt][j] = 0.f;
    run_mainloop<PW1, 8>(smbase, TA1, TB1, 2 * TA1, wrow, nt0, lane, acc);
    __syncthreads();

    {   // h1 = relu(acc+b1) -> restage as KD=64 tiles (overlay)
        const int rA = lane >> 2, kq = lane & 3;
        const int rlo = wrow + rA, rhi = rlo + 8;
#pragma unroll
        for (int nt = 0; nt < 4; nt++) {
            int col = (nt0 + nt) * 8 + kq * 2;
            float v0x = fmaxf(acc[nt][0] + bsh1[col], 0.f);
            float v0y = fmaxf(acc[nt][1] + bsh1[col + 1], 0.f);
            float v1x = fmaxf(acc[nt][2] + bsh1[col], 0.f);
            float v1y = fmaxf(acc[nt][3] + bsh1[col + 1], 0.f);
            int w = col >> 1;
            uint32_t h0, l0, h1, l1;
            split2(v0x, v0y, h0, l0);
            split2(v1x, v1y, h1, l1);
            sm[rlo * PW2 + w]       = h0;
            sm[TA2 + rlo * PW2 + w] = l0;
            sm[rhi * PW2 + w]       = h1;
            sm[TA2 + rhi * PW2 + w] = l1;
        }
    }
    for (int q = tid; q < 64 * 16; q += 512) {
        int r = q >> 4, c = (q & 15) * 4;
        float4 v = *(const float4*)(W2 + (long)r * 64 + c);
        split4store(sm + 2 * TA2, sm + 2 * TA2 + TB2, r * PW2 + (c >> 1), v);
    }
    __syncthreads();

    float acc2[4][4];
#pragma unroll
    for (int nt = 0; nt < 4; nt++)
#pragma unroll
        for (int j = 0; j < 4; j++) acc2[nt][j] = 0.f;
    run_mainloop<PW2, 4>(smbase, TA2, TB2, 2 * TA2, wrow, nt0, lane, acc2);

    const int rA = lane >> 2, kq = lane & 3;
    const long r_lo = row0 + wrow + rA, r_hi = r_lo + 8;
#pragma unroll
    for (int nt = 0; nt < 4; nt++) {
        int col = (nt0 + nt) * 8 + kq * 2;
        float2 v0 = make_float2(fmaxf(acc2[nt][0] + bsh2[col], 0.f),
                                fmaxf(acc2[nt][1] + bsh2[col + 1], 0.f));
        float2 v1 = make_float2(fmaxf(acc2[nt][2] + bsh2[col], 0.f),
                                fmaxf(acc2[nt][3] + bsh2[col + 1], 0.f));
        if (r_lo < NN) *(float2*)(out + r_lo * 64 + col) = v0;
        if (r_hi < NN) *(float2*)(out + r_hi * 64 + col) = v1;
    }
}

// =========== fused back MLP + head ===========
__global__ void __launch_bounds__(512) mlp_back_kernel(const float* __restrict__ X,
                                                       const float* __restrict__ W3,
                                                       const float* __restrict__ b3,
                                                       const float* __restrict__ W4,
                                                       const float* __restrict__ b4,
                                                       float* __restrict__ out) {
    constexpr int PW = 36, TA = 128 * PW, TB = 64 * PW;
    extern __shared__ uint32_t sm[];
    __shared__ float bsh[64], W4sh[128], b4sh[2];
    __shared__ float hp[2][128][2];

    const int tid = threadIdx.x;
    const long row0 = (long)blockIdx.x * 128;
    if (tid < 64)  bsh[tid] = b3[tid];
    if (tid < 128) W4sh[tid] = W4[tid];
    if (tid < 2)   b4sh[tid] = b4[tid];

    for (int q = tid; q < 128 * 16; q += 512) {
        int r = q >> 4, c = (q & 15) * 4;
        long gr = row0 + r; if (gr >= NN) gr = NN - 1;
        float4 v = *(const float4*)(X + gr * 64 + c);
        split4store(sm, sm + TA, r * PW + (c >> 1), v);
    }
    for (int q = tid; q < 64 * 16; q += 512) {
        int r = q >> 4, c = (q & 15) * 4;
        float4 v = *(const float4*)(W3 + (long)r * 64 + c);
        split4store(sm + 2 * TA, sm + 2 * TA + TB, r * PW + (c >> 1), v);
    }
    __syncthreads();

    const int warp = tid >> 5, lane = tid & 31;
    const int wrow = (warp & 7) * 16;
    const int nt0w = warp >> 3;
    const int nt0 = nt0w * 4;
    const uint32_t smbase = (uint32_t)__cvta_generic_to_shared(sm);

    float acc[4][4];
#pragma unroll
    for (int nt = 0; nt < 4; nt++)
#pragma unroll
        for (int j = 0; j < 4; j++) acc[nt][j] = 0.f;
    run_mainloop<PW, 4>(smbase, TA, TB, 2 * TA, wrow, nt0, lane, acc);

    const int rA = lane >> 2, kq = lane & 3;
    float p00 = 0.f, p01 = 0.f, p10 = 0.f, p11 = 0.f;
#pragma unroll
    for (int nt = 0; nt < 4; nt++) {
        int c = (nt0 + nt) * 8 + kq * 2;
        float v0x = fmaxf(acc[nt][0] + bsh[c], 0.f);
        float v0y = fmaxf(acc[nt][1] + bsh[c + 1], 0.f);
        float v1x = fmaxf(acc[nt][2] + bsh[c], 0.f);
        float v1y = fmaxf(acc[nt][3] + bsh[c + 1], 0.f);
        float w0a = W4sh[c], w0b = W4sh[c + 1];
        float w1a = W4sh[64 + c], w1b = W4sh[64 + c + 1];
        p00 = fmaf(v0x, w0a, fmaf(v0y, w0b, p00));
        p01 = fmaf(v0x, w1a, fmaf(v0y, w1b, p01));
        p10 = fmaf(v1x, w0a, fmaf(v1y, w0b, p10));
        p11 = fmaf(v1x, w1a, fmaf(v1y, w1b, p11));
    }
    p00 += __shfl_xor_sync(0xffffffffu, p00, 1); p00 += __shfl_xor_sync(0xffffffffu, p00, 2);
    p01 += __shfl_xor_sync(0xffffffffu, p01, 1); p01 += __shfl_xor_sync(0xffffffffu, p01, 2);
    p10 += __shfl_xor_sync(0xffffffffu, p10, 1); p10 += __shfl_xor_sync(0xffffffffu, p10, 2);
    p11 += __shfl_xor_sync(0xffffffffu, p11, 1); p11 += __shfl_xor_sync(0xffffffffu, p11, 2);
    if (kq == 0) {
        hp[nt0w][wrow + rA][0] = p00;
        hp[nt0w][wrow + rA][1] = p01;
        hp[nt0w][wrow + rA + 8][0] = p10;
        hp[nt0w][wrow + rA + 8][1] = p11;
    }
    __syncthreads();
    if (tid < 256) {
        int row = tid >> 1, cls = tid & 1;
        long gr = row0 + row;
        if (gr < NN) out[gr * 2 + cls] = hp[0][row][cls] + hp[1][row][cls] + b4sh[cls];
    }
}

// ------------- SpMM on pre-scaled input: S[n,:] = dinv[n] * sum_{e: dst=n} Xs[src,:] -------------
// Warp per node; int4 bucket loads; 4 independent float2 ADD chains (round-12 shape).
// Souts (optional): S * dinv for the next spmm hop.
__global__ void __launch_bounds__(256) spmm_norm_kernel(const float* __restrict__ Xs,
                                                        float* __restrict__ Sout,
                                                        float* __restrict__ Souts) {
    int n = (blockIdx.x * 256 + threadIdx.x) >> 5;
    if (n >= NN) return;
    int lane = threadIdx.x & 31;
    int cnt = g_cnt[n];
    if (cnt > BCAP) cnt = BCAP;
    const int4* bk4 = (const int4*)&g_bucket[(size_t)n * BCAP];
    const float* xb = Xs + (size_t)lane * 2;
    float2 a0 = make_float2(0.f, 0.f), a1 = make_float2(0.f, 0.f);
    float2 a2 = make_float2(0.f, 0.f), a3 = make_float2(0.f, 0.f);
    int i = 0;
    for (; i + 3 < cnt; i += 4) {
        int4 s4 = bk4[i >> 2];
        float2 v0 = *(const float2*)(xb + (size_t)s4.x * 64);
        float2 v1 = *(const float2*)(xb + (size_t)s4.y * 64);
        float2 v2 = *(const float2*)(xb + (size_t)s4.z * 64);
        float2 v3 = *(const float2*)(xb + (size_t)s4.w * 64);
        a0.x += v0.x; a0.y += v0.y;
        a1.x += v1.x; a1.y += v1.y;
        a2.x += v2.x; a2.y += v2.y;
        a3.x += v3.x; a3.y += v3.y;
    }
    const int* bk = (const int*)bk4;
    for (; i < cnt; i++) {
        int s = bk[i];
        float2 v = *(const float2*)(xb + (size_t)s * 64);
        a0.x += v.x; a0.y += v.y;
    }
    float dn = g_dinv[n];
    float2 acc;
    acc.x = ((a0.x + a1.x) + (a2.x + a3.x)) * dn;
    acc.y = ((a0.y + a1.y) + (a2.y + a3.y)) * dn;
    *(float2*)(Sout + (size_t)n * 64 + lane * 2) = acc;
    if (Souts)
        *(float2*)(Souts + (size_t)n * 64 + lane * 2) = make_float2(acc.x * dn, acc.y * dn);
}

// ---------------- launch ----------------
extern "C" void kernel_launch(void* const* d_in, const int* in_sizes, int n_in,
                              void* d_out, int out_size) {
    const float* in_feat = (const float*)d_in[0];
    const int*   src     = (const int*)d_in[1];
    const int*   dst     = (const int*)d_in[2];
    const float* W1  = (const float*)d_in[3];
    const float* b1  = (const float*)d_in[4];
    const float* W2  = (const float*)d_in[5];
    const float* b2  = (const float*)d_in[6];
    const float* Wc1 = (const float*)d_in[7];
    const float* bc1 = (const float*)d_in[8];
    const float* Wc2 = (const float*)d_in[9];
    const float* bc2 = (const float*)d_in[10];
    const float* W3  = (const float*)d_in[11];
    const float* b3  = (const float*)d_in[12];
    const float* W4  = (const float*)d_in[13];
    const float* b4  = (const float*)d_in[14];
    float* out = (float*)d_out;

    float *h2, *h2s, *S1, *S1s, *S2, *c1, *c1s, *c2;
    int* cnt;
    cudaGetSymbolAddress((void**)&h2,  g_h2);
    cudaGetSymbolAddress((void**)&h2s, g_h2s);
    cudaGetSymbolAddress((void**)&S1,  g_S1);
    cudaGetSymbolAddress((void**)&S1s, g_S1s);
    cudaGetSymbolAddress((void**)&S2,  g_S2);
    cudaGetSymbolAddress((void**)&c1,  g_c1);
    cudaGetSymbolAddress((void**)&c1s, g_c1s);
    cudaGetSymbolAddress((void**)&c2,  g_c2);
    cudaGetSymbolAddress((void**)&cnt, g_cnt);

    const int FRONT_SMEM = (2 * 128 * 68 + 2 * 64 * 68) * 4;   // 104448
    const int BACK_SMEM  = (2 * 128 * 36 + 2 * 64 * 36) * 4;   // 55296
    const int CAT_SMEM   = (2 * 128 * 52 + 2 * 64 * 52) * 4;   // 79872

    cudaFuncSetAttribute(front_build_kernel, cudaFuncAttributeMaxDynamicSharedMemorySize, FRONT_SMEM);
    cudaFuncSetAttribute(mlp_back_kernel,    cudaFuncAttributeMaxDynamicSharedMemorySize, BACK_SMEM);
    cudaFuncSetAttribute(gemm_mma_kernel<192, 96, 1>, cudaFuncAttributeMaxDynamicSharedMemorySize, CAT_SMEM);

    const int GW = (NN * 32 + 255) / 256;   // warp-per-node kernels

    // zero counts, then fused front-MLP || bucket-build
    cudaMemsetAsync(cnt, 0, NN * sizeof(int));
    front_build_kernel<<<GT + GB, 512, FRONT_SMEM>>>(in_feat, W1, b1, W2, b2, h2, src, dst);
    dinv_scale_kernel<<<GW, 256>>>(h2, h2s);     // g_dinv + h2s = h2*dinv

    // ChebConv 1
    spmm_norm_kernel<<<GW, 256>>>(h2s, S1, S1s);
    spmm_norm_kernel<<<GW, 256>>>(S1s, S2, nullptr);
    gemm_mma_kernel<192, 96, 1><<<GT, 512, CAT_SMEM>>>(h2, S1, S2, Wc1, bc1, c1, c1s, 1);

    // ChebConv 2
    spmm_norm_kernel<<<GW, 256>>>(c1s, S1, S1s);
    spmm_norm_kernel<<<GW, 256>>>(S1s, S2, nullptr);
    gemm_mma_kernel<192, 96, 1><<<GT, 512, CAT_SMEM>>>(c1, S1, S2, Wc2, bc2, c2, nullptr, 1);

    // fused back MLP + head
    mlp_back_kernel<<<GT, 512, BACK_SMEM>>>(c2, W3, b3, W4, b4, out);
}